// round 14
// baseline (speedup 1.0000x reference)
#include <cuda_runtime.h>
#include <cuda_fp16.h>
#include <math.h>
#include <stdint.h>

// ---------------- problem constants ----------------
#define B_ 128
#define S_ 256
#define H_ 128

// ---------------- device scratch (allocation-free) ----------------
__device__ __half g_ETh[B_ * 256 * 256];      // [b][n=256][s=256] E^T in fp16 (B-operand of MSG)
__device__ __half g_MSGh[B_ * S_ * 256];      // [m=32768][256] fp16
__device__ float  g_H2[B_ * S_ * H_];         // new hidden (fp32)
__device__ float  g_Q12[B_ * S_ * 256];       // [m][256] q1|q2
__device__ float  g_WET[256 * 128];           // [n][k]  (W_ein ; W_eout)
__device__ float  g_WQT[256 * 128];           // [n][k]  (W_q1 ; W_q2)
__device__ float  g_WBT[512 * 384];           // [n'][k] fused GRU weight, gate-interleaved n' = 4*j + g
__device__ float  g_biasE[256];
__device__ float  g_biasQ[256];
__device__ float  g_biasIO[256];
__device__ float  g_biasBig[512];             // gate-interleaved
__device__ float  g_q0v[B_ * H_];
__device__ int    g_nvalid[B_];

// ---------------- helpers ----------------
__device__ __forceinline__ uint2 cvt_pack_f16(float4 v) {
    __half2 a = __floats2half2_rn(v.x, v.y);
    __half2 b = __floats2half2_rn(v.z, v.w);
    return make_uint2(*reinterpret_cast<uint32_t*>(&a), *reinterpret_cast<uint32_t*>(&b));
}

#define LDSM4(r, a) \
    asm volatile("ldmatrix.sync.aligned.m8n8.x4.shared.b16 {%0,%1,%2,%3}, [%4];" \
                 : "=r"((r)[0]), "=r"((r)[1]), "=r"((r)[2]), "=r"((r)[3]) : "r"(a))

#define MMA_F16(c, a, b) \
    asm volatile("mma.sync.aligned.m16n8k16.row.col.f32.f16.f16.f32 " \
                 "{%0,%1,%2,%3}, {%4,%5,%6,%7}, {%8,%9}, {%0,%1,%2,%3};" \
                 : "+f"((c)[0]), "+f"((c)[1]), "+f"((c)[2]), "+f"((c)[3]) \
                 : "r"((a)[0]), "r"((a)[1]), "r"((a)[2]), "r"((a)[3]), \
                   "r"((b)[0]), "r"((b)[1]))

// ---------------- weight prep ----------------
__global__ void prep_kernel(const float* __restrict__ w_ih, const float* __restrict__ w_hh,
                            const float* __restrict__ b_ih, const float* __restrict__ b_hh,
                            const float* __restrict__ W_ein, const float* __restrict__ b_ein,
                            const float* __restrict__ W_eout, const float* __restrict__ b_eout,
                            const float* __restrict__ b_iah, const float* __restrict__ b_oah,
                            const float* __restrict__ W_q1, const float* __restrict__ b_q1,
                            const float* __restrict__ W_q2, const float* __restrict__ b_q2) {
    int idx = blockIdx.x * blockDim.x + threadIdx.x;
    if (idx < 512 * 384) {  // g_WBT [n'][k], gate-interleaved: n' = 4*j + g
        int np = idx / 384, k = idx - np * 384;
        int j = np >> 2, g = np & 3;
        int on = (g == 0) ? j : (g == 1) ? 128 + j : (g == 2) ? 256 + j : 384 + j;
        float v;
        if (on < 256)      v = (k < 256) ? w_ih[on * 256 + k] : w_hh[on * 128 + (k - 256)];
        else if (on < 384) v = (k < 256) ? w_ih[on * 256 + k] : 0.f;
        else               v = (k >= 256) ? w_hh[(on - 128) * 128 + (k - 256)] : 0.f;
        g_WBT[idx] = v;
    }
    if (idx < 256 * 128) {  // [n][k]
        int n = idx >> 7, k = idx & 127;
        g_WET[idx] = (n < 128) ? W_ein[n * 128 + k] : W_eout[(n - 128) * 128 + k];
        g_WQT[idx] = (n < 128) ? W_q1[n * 128 + k]  : W_q2[(n - 128) * 128 + k];
    }
    if (idx < 512) {
        int j = idx >> 2, g = idx & 3;
        int on = (g == 0) ? j : (g == 1) ? 128 + j : (g == 2) ? 256 + j : 384 + j;
        g_biasBig[idx] = (on < 256) ? b_ih[on] + b_hh[on] : (on < 384) ? b_ih[on] : b_hh[on - 128];
    }
    if (idx < 256) {
        g_biasE[idx]  = (idx < 128) ? b_ein[idx] : b_eout[idx - 128];
        g_biasQ[idx]  = (idx < 128) ? b_q1[idx]  : b_q2[idx - 128];
        g_biasIO[idx] = (idx < 128) ? b_iah[idx] : b_oah[idx - 128];
    }
}

// ---------------- generic fp16 warp-MMA GEMM, double-buffered + pipelined ----------------
// C[M,N] = X[M,K] @ Bt[N,K]^T (+bias).  CTA tile 128x128, chunks of K=32.
// MODE 0: E   = hidden @ WET^T         -> g_ETh (transposed out, fp16, +biasE)
// MODE 1: MSG = A[b] @ ET[b]^T         -> g_MSGh (fp16, +biasIO)
// MODE 2: Ggates = [MSG|hidden] @ WBT^T, gate-interleaved; FUSED GRU -> g_H2 (fp32)
// MODE 3: Q12 = H2 @ WQT^T             -> g_Q12 (+biasQ)
#define LDS_ 40        // row stride in halfs (80 bytes): conflict-free for STS + ldmatrix
#define PLANE_H 5120   // halfs per plane (128 rows x 40)

template<int MODE>
__global__ void __launch_bounds__(256, 2) gemm_mma(const float* __restrict__ Xext) {
    __shared__ __align__(16) uint16_t smraw[2][2 * PLANE_H];  // [buf][X|B plane]  40KB
    uint32_t smb = (uint32_t)__cvta_generic_to_shared(&smraw[0][0]);

    int tid = threadIdx.x;
    int wid = tid >> 5, lane = tid & 31;
    int n0 = blockIdx.x * 128;
    int m0 = blockIdx.y * 128;
    int bz = blockIdx.z;

    const int K1 = (MODE == 1) ? 256 : (MODE == 2) ? 384 : 128;

    const int wm0 = (wid & 3) * 32;   // warp m-offset in CTA tile
    const int wn0 = (wid >> 2) * 64;  // warp n-offset

    float acc[2][8][4];
#pragma unroll
    for (int i = 0; i < 2; i++)
#pragma unroll
        for (int j = 0; j < 8; j++)
#pragma unroll
            for (int c = 0; c < 4; c++) acc[i][j][c] = 0.f;

    int r8 = tid >> 3;            // 0..31 (row within 32-row pass)
    int c4 = (tid & 7) * 4;       // element col (floats or halfs) within 32-wide chunk

    // ldmatrix per-lane address components
    int am = lane & 15;
    int akh = (lane >> 4) << 3;
    int bnl = (lane & 7) + ((lane >> 4) << 3);
    int bkh = ((lane >> 3) & 1) << 3;

    uint2 xh[4], bh[4];  // packed-half prefetch registers

    // ---- prefetch one chunk (X + B) into packed-half registers ----
    auto ldg_chunk = [&](int kt) {
        // X side
        if (MODE == 2) {
            if (kt < 256) {
#pragma unroll
                for (int p = 0; p < 4; p++)
                    xh[p] = *reinterpret_cast<const uint2*>(
                        g_MSGh + (size_t)(m0 + p * 32 + r8) * 256 + kt + c4);
            } else {
#pragma unroll
                for (int p = 0; p < 4; p++)
                    xh[p] = cvt_pack_f16(*reinterpret_cast<const float4*>(
                        Xext + (size_t)(m0 + p * 32 + r8) * 128 + (kt - 256) + c4));
            }
        } else {
            const float* Xs = (MODE == 1) ? Xext + (size_t)bz * 131072
                            : (MODE == 3) ? g_H2 : Xext;
            const int ldx = (MODE == 1) ? 512 : 128;
            const int col = kt + ((MODE == 1 && n0 >= 128) ? 256 : 0);
#pragma unroll
            for (int p = 0; p < 4; p++)
                xh[p] = cvt_pack_f16(*reinterpret_cast<const float4*>(
                    Xs + (size_t)(m0 + p * 32 + r8) * ldx + col + c4));
        }
        // B side
        if (MODE == 1) {
            const __half* Bh = g_ETh + (size_t)bz * 65536;
#pragma unroll
            for (int p = 0; p < 4; p++)
                bh[p] = *reinterpret_cast<const uint2*>(
                    Bh + (size_t)(n0 + p * 32 + r8) * 256 + kt + c4);
        } else {
            const float* Bt = (MODE == 0) ? g_WET : (MODE == 2) ? g_WBT : g_WQT;
            const int ldb = (MODE == 2) ? 384 : 128;
#pragma unroll
            for (int p = 0; p < 4; p++)
                bh[p] = cvt_pack_f16(*reinterpret_cast<const float4*>(
                    Bt + (size_t)(n0 + p * 32 + r8) * ldb + kt + c4));
        }
    };
    auto sts_chunk = [&](int pb) {
#pragma unroll
        for (int p = 0; p < 4; p++) {
            int off = (p * 32 + r8) * LDS_ + c4;
            *reinterpret_cast<uint2*>(&smraw[pb][off]) = xh[p];
            *reinterpret_cast<uint2*>(&smraw[pb][off + PLANE_H]) = bh[p];
        }
    };

    // ---- prologue ----
    ldg_chunk(0);
    sts_chunk(0);
    __syncthreads();

    const int nc = K1 >> 5;
    int pb = 0;
    for (int c = 0; c < nc; c++) {
        bool more = (c + 1 < nc);
        if (more) ldg_chunk((c + 1) * 32);

        // ---- compute chunk from buffer pb: 2 k-steps of 16 ----
        uint32_t bufb = smb + (uint32_t)(pb * 2 * PLANE_H * 2);
#pragma unroll
        for (int ks = 0; ks < 32; ks += 16) {
            uint32_t af[2][4];
#pragma unroll
            for (int i = 0; i < 2; i++) {
                uint32_t aoff = bufb + (uint32_t)((wm0 + i * 16 + am) * LDS_ + ks + akh) * 2;
                LDSM4(af[i], aoff);
            }
#pragma unroll
            for (int jp = 0; jp < 4; jp++) {
                uint32_t boff = bufb + (uint32_t)(PLANE_H + (wn0 + jp * 16 + bnl) * LDS_ + ks + bkh) * 2;
                uint32_t bf[4];
                LDSM4(bf, boff);
#pragma unroll
                for (int i = 0; i < 2; i++) {
#pragma unroll
                    for (int jj = 0; jj < 2; jj++) {
                        MMA_F16(acc[i][jp * 2 + jj], af[i], (bf + jj * 2));
                    }
                }
            }
        }

        if (more) sts_chunk(pb ^ 1);
        __syncthreads();
        pb ^= 1;
    }

    // ---- epilogues ----
    int mrow = m0 + wm0 + (lane >> 2);       // first of the two m-rows per tile
    int ncol = wn0 + (lane & 3) * 2;         // within-CTA n offset (add j*8)

    if (MODE == 2) {
        // Fused GRU: acc holds gate-interleaved preactivations (before bias).
        // n' = 4*jcol + gate; pairs (n,n+1) are gates{0,1} (even lane) / {2,3} (odd lane).
        float* sh = reinterpret_cast<float*>(&smraw[0][0]);   // hidden tile [128][32]
        float* shH2 = sh + 4096;                              // H2 tile [128][32]
        int jc0 = n0 >> 2;
        // stage hidden tile (coalesced)
#pragma unroll
        for (int p = 0; p < 4; p++) {
            int r = p * 32 + (tid >> 3), cg = (tid & 7) * 4;
            *reinterpret_cast<float4*>(&sh[r * 32 + cg]) =
                *reinterpret_cast<const float4*>(Xext + (size_t)(m0 + r) * 128 + jc0 + cg);
        }
        __syncthreads();
#pragma unroll
        for (int i = 0; i < 2; i++) {
#pragma unroll
            for (int j = 0; j < 8; j++) {
                int n = n0 + ncol + 8 * j;
                float* cc = acc[i][j];
                float g0 = cc[0] + g_biasBig[n];       // row m,   col n
                float g1 = cc[1] + g_biasBig[n + 1];   // row m,   col n+1
                float g2 = cc[2] + g_biasBig[n];       // row m+8, col n
                float g3 = cc[3] + g_biasBig[n + 1];   // row m+8, col n+1
                // exchange between lane pairs (xor 1): even lane ends with row m
                // gates 0..3; odd lane with row m+8 gates 0..3.
                float s0 = (lane & 1) ? g0 : g2;
                float s1 = (lane & 1) ? g1 : g3;
                float r0 = __shfl_xor_sync(0xFFFFFFFFu, s0, 1);
                float r1 = __shfl_xor_sync(0xFFFFFFFFu, s1, 1);
                float a0, a1, a2, a3;
                if (lane & 1) { a0 = r0; a1 = r1; a2 = g2; a3 = g3; }
                else          { a0 = g0; a1 = g1; a2 = r0; a3 = r1; }
                int jl = (ncol + 8 * j) >> 2;                       // 0..31
                int rl = wm0 + (lane >> 2) + 16 * i + ((lane & 1) ? 8 : 0);
                float hv = sh[rl * 32 + jl];
                float rg = 1.f / (1.f + expf(-a0));
                float zg = 1.f / (1.f + expf(-a1));
                float ng = tanhf(a2 + rg * a3);
                shH2[rl * 32 + jl] = hv - zg * (hv - ng);
            }
        }
        __syncthreads();
        // coalesced H2 writeback
#pragma unroll
        for (int p = 0; p < 4; p++) {
            int r = p * 32 + (tid >> 3), cg = (tid & 7) * 4;
            *reinterpret_cast<float4*>(g_H2 + (size_t)(m0 + r) * 128 + jc0 + cg) =
                *reinterpret_cast<float4*>(&shH2[r * 32 + cg]);
        }
    } else if (MODE == 0) {
        // transposed fp16 out: g_ETh[b][n][s]
        int b = mrow >> 8, s = mrow & 255;
        __half* o = g_ETh + (size_t)b * 65536;
#pragma unroll
        for (int i = 0; i < 2; i++) {
            int s0 = s + i * 16;
#pragma unroll
            for (int j = 0; j < 8; j++) {
                int n = n0 + ncol + j * 8;
                float* cc = acc[i][j];
                o[(size_t)n * 256 + s0]           = __float2half_rn(cc[0] + g_biasE[n]);
                o[(size_t)(n + 1) * 256 + s0]     = __float2half_rn(cc[1] + g_biasE[n + 1]);
                o[(size_t)n * 256 + s0 + 8]       = __float2half_rn(cc[2] + g_biasE[n]);
                o[(size_t)(n + 1) * 256 + s0 + 8] = __float2half_rn(cc[3] + g_biasE[n + 1]);
            }
        }
    } else if (MODE == 1) {
        size_t rbase = (size_t)bz * 256 + mrow;
#pragma unroll
        for (int i = 0; i < 2; i++) {
            __half* o0 = g_MSGh + (rbase + i * 16) * 256;
            __half* o1 = o0 + 8 * 256;
#pragma unroll
            for (int j = 0; j < 8; j++) {
                int n = n0 + ncol + j * 8;
                float* cc = acc[i][j];
                *reinterpret_cast<__half2*>(o0 + n) =
                    __floats2half2_rn(cc[0] + g_biasIO[n], cc[1] + g_biasIO[n + 1]);
                *reinterpret_cast<__half2*>(o1 + n) =
                    __floats2half2_rn(cc[2] + g_biasIO[n], cc[3] + g_biasIO[n + 1]);
            }
        }
    } else {  // MODE 3
        size_t rbase = (size_t)mrow;
#pragma unroll
        for (int i = 0; i < 2; i++) {
            float* o0 = g_Q12 + (rbase + i * 16) * 256;
            float* o1 = o0 + 8 * 256;
#pragma unroll
            for (int j = 0; j < 8; j++) {
                int n = n0 + ncol + j * 8;
                float* cc = acc[i][j];
                float2 v0 = make_float2(cc[0] + g_biasQ[n], cc[1] + g_biasQ[n + 1]);
                float2 v1 = make_float2(cc[2] + g_biasQ[n], cc[3] + g_biasQ[n + 1]);
                *reinterpret_cast<float2*>(o0 + n) = v0;
                *reinterpret_cast<float2*>(o1 + n) = v1;
            }
        }
    }
}

// ---------------- nvalid + ht1 gather + q0 GEMV ----------------
__global__ void q0_kernel(const int* __restrict__ mask,
                          const float* __restrict__ W_q0, const float* __restrict__ b_q0) {
    __shared__ int ired[128];
    __shared__ float ht[128];
    int b = blockIdx.x, t = threadIdx.x;
    ired[t] = mask[b * 256 + t] + mask[b * 256 + 128 + t];
    __syncthreads();
    for (int off = 64; off; off >>= 1) {
        if (t < off) ired[t] += ired[t + off];
        __syncthreads();
    }
    int nv = ired[0];
    int li = nv - 1;
    ht[t] = g_H2[((size_t)b * 256 + li) * 128 + t];
    __syncthreads();
    float acc = 0.f;
#pragma unroll 8
    for (int k = 0; k < 128; k++) acc += ht[k] * W_q0[t * 128 + k];
    g_q0v[b * 128 + t] = acc + b_q0[t];
    if (t == 0) g_nvalid[b] = nv;
}

// ---------------- collapsed attention readout ----------------
__global__ void attn_kernel(float* __restrict__ out) {
    __shared__ float q0s[128];
    __shared__ float sc[8][256];
    __shared__ float red[256];
    int b = blockIdx.x, t = threadIdx.x;
    const float* Q = g_Q12 + (size_t)b * 256 * 256;
    if (t < 128) q0s[t] = g_q0v[b * 128 + t];
    __syncthreads();
    for (int e = t; e < 2048; e += 256) {
        int h = e >> 8, j = e & 255;
        const float* q1 = Q + j * 256 + h * 16;
        float s = 0.f;
#pragma unroll
        for (int d = 0; d < 16; d++) s += q0s[h * 16 + d] * q1[d];
        sc[h][j] = 1.f / (1.f + expf(-s));
    }
    __syncthreads();
    {
        int w = t >> 5, lane = t & 31;
        float sum = 0.f;
        for (int j = lane; j < 256; j += 32) {
            float e = expf(sc[w][j]);
            sc[w][j] = e;
            sum += e;
        }
#pragma unroll
        for (int o = 16; o; o >>= 1) sum += __shfl_xor_sync(0xFFFFFFFFu, sum, o);
        float inv = 1.f / sum;
        for (int j = lane; j < 256; j += 32) sc[w][j] *= inv;
    }
    __syncthreads();
    {
        int j = t;
        float e[8], s = 0.f;
#pragma unroll
        for (int h = 0; h < 8; h++) { e[h] = expf(2.f * sc[h][j]); s += e[h]; }
        float inv = 1.f / s;
#pragma unroll
        for (int h = 0; h < 8; h++) sc[h][j] = e[h] * inv;
    }
    __syncthreads();
    {
        int o = t & 127, half = t >> 7;
        int h = o >> 4, d = o & 15;
        float acc = 0.f;
        int j0 = half * 128;
        for (int j = j0; j < j0 + 128; j++)
            acc += sc[h][j] * Q[j * 256 + 128 + h * 16 + d];
        red[t] = acc;
    }
    __syncthreads();
    if (t < 128) {
        float y = red[t] + red[t + 128];
        out[b * 128 + t] = (float)g_nvalid[b] * y;
    }
}

// ---------------- launch ----------------
extern "C" void kernel_launch(void* const* d_in, const int* in_sizes, int n_in,
                              void* d_out, int out_size) {
    const float* A      = (const float*)d_in[0];
    const float* hidden = (const float*)d_in[1];
    const int*   mask   = (const int*)d_in[2];
    const float* w_ih   = (const float*)d_in[3];
    const float* w_hh   = (const float*)d_in[4];
    const float* b_ih   = (const float*)d_in[5];
    const float* b_hh   = (const float*)d_in[6];
    const float* b_iah  = (const float*)d_in[7];
    const float* b_oah  = (const float*)d_in[8];
    const float* W_ein  = (const float*)d_in[9];
    const float* b_ein  = (const float*)d_in[10];
    const float* W_eout = (const float*)d_in[11];
    const float* b_eout = (const float*)d_in[12];
    const float* W_q0   = (const float*)d_in[13];
    const float* b_q0   = (const float*)d_in[14];
    const float* W_q1   = (const float*)d_in[15];
    const float* b_q1   = (const float*)d_in[16];
    const float* W_q2   = (const float*)d_in[17];
    const float* b_q2   = (const float*)d_in[18];
    float* out = (float*)d_out;

    // 0) weight prep (gate-interleaved WBT)
    prep_kernel<<<768, 256>>>(w_ih, w_hh, b_ih, b_hh, W_ein, b_ein, W_eout, b_eout,
                              b_iah, b_oah, W_q1, b_q1, W_q2, b_q2);
    // 1) E^T = (hidden @ WET^T)^T + biasE      -> g_ETh (fp16)
    gemm_mma<0><<<dim3(2, 256, 1), 256>>>(hidden);
    // 2) MSG = A @ E + biasIO (batched)        -> g_MSGh (fp16)
    gemm_mma<1><<<dim3(2, 2, 128), 256>>>(A);
    // 3) gates = [MSG|hidden] @ WBT^T, fused GRU -> g_H2
    gemm_mma<2><<<dim3(4, 256, 1), 256>>>(hidden);
    // 4) nvalid, ht1, q0
    q0_kernel<<<128, 128>>>(mask, W_q0, b_q0);
    // 5) Q12 = H2 @ WQT^T + biasQ -> g_Q12
    gemm_mma<3><<<dim3(2, 256, 1), 256>>>(nullptr);
    // 6) collapsed attention + readout
    attn_kernel<<<128, 256>>>(out);
}

// round 15
// speedup vs baseline: 1.1337x; 1.1337x over previous
#include <cuda_runtime.h>
#include <cuda_fp16.h>
#include <math.h>
#include <stdint.h>

// ---------------- problem constants ----------------
#define B_ 128
#define S_ 256
#define H_ 128

// ---------------- device scratch (allocation-free) ----------------
__device__ __align__(16) __half g_ETh[B_ * 256 * 256];   // [b][n][s] E^T fp16 (B-op of MSG)
__device__ __align__(16) __half g_MSGh[B_ * S_ * 256];   // [m][256] fp16
__device__ __align__(16) __half g_Hh[B_ * S_ * H_];      // fp16 copy of hidden
__device__ __align__(16) __half g_H2h[B_ * S_ * H_];     // fp16 copy of new hidden
__device__ float  g_H2[B_ * S_ * H_];                    // new hidden (fp32, for q0)
__device__ float  g_Q12[B_ * S_ * 256];                  // [m][256] q1|q2
__device__ __align__(16) __half g_WETh[256 * 128];       // [n][k]
__device__ __align__(16) __half g_WQTh[256 * 128];       // [n][k]
__device__ __align__(16) __half g_WBTh[512 * 384];       // [n'][k], gate-interleaved n' = 4*j + g
__device__ float  g_biasE[256];
__device__ float  g_biasQ[256];
__device__ float  g_biasIO[256];
__device__ float  g_biasBig[512];                        // gate-interleaved
__device__ float  g_q0v[B_ * H_];
__device__ int    g_nvalid[B_];

// ---------------- helpers ----------------
__device__ __forceinline__ uint2 cvt_pack_f16(float4 v) {
    __half2 a = __floats2half2_rn(v.x, v.y);
    __half2 b = __floats2half2_rn(v.z, v.w);
    return make_uint2(*reinterpret_cast<uint32_t*>(&a), *reinterpret_cast<uint32_t*>(&b));
}

__device__ __forceinline__ void cp_async16(uint32_t dst, const void* src) {
    asm volatile("cp.async.cg.shared.global [%0], [%1], 16;" :: "r"(dst), "l"(src));
}
#define CP_COMMIT() asm volatile("cp.async.commit_group;" ::: "memory")
#define CP_WAIT0()  asm volatile("cp.async.wait_group 0;" ::: "memory")

#define LDSM4(r, a) \
    asm volatile("ldmatrix.sync.aligned.m8n8.x4.shared.b16 {%0,%1,%2,%3}, [%4];" \
                 : "=r"((r)[0]), "=r"((r)[1]), "=r"((r)[2]), "=r"((r)[3]) : "r"(a))

#define MMA_F16(c, a, b) \
    asm volatile("mma.sync.aligned.m16n8k16.row.col.f32.f16.f16.f32 " \
                 "{%0,%1,%2,%3}, {%4,%5,%6,%7}, {%8,%9}, {%0,%1,%2,%3};" \
                 : "+f"((c)[0]), "+f"((c)[1]), "+f"((c)[2]), "+f"((c)[3]) \
                 : "r"((a)[0]), "r"((a)[1]), "r"((a)[2]), "r"((a)[3]), \
                   "r"((b)[0]), "r"((b)[1]))

// ---------------- weight prep (fp16 weights; WBT gate-interleaved) ----------------
__global__ void prep_kernel(const float* __restrict__ w_ih, const float* __restrict__ w_hh,
                            const float* __restrict__ b_ih, const float* __restrict__ b_hh,
                            const float* __restrict__ W_ein, const float* __restrict__ b_ein,
                            const float* __restrict__ W_eout, const float* __restrict__ b_eout,
                            const float* __restrict__ b_iah, const float* __restrict__ b_oah,
                            const float* __restrict__ W_q1, const float* __restrict__ b_q1,
                            const float* __restrict__ W_q2, const float* __restrict__ b_q2) {
    int idx = blockIdx.x * blockDim.x + threadIdx.x;
    if (idx < 512 * 384) {  // g_WBTh [n'][k], n' = 4*j + g
        int np = idx / 384, k = idx - np * 384;
        int j = np >> 2, g = np & 3;
        int on = (g == 0) ? j : (g == 1) ? 128 + j : (g == 2) ? 256 + j : 384 + j;
        float v;
        if (on < 256)      v = (k < 256) ? w_ih[on * 256 + k] : w_hh[on * 128 + (k - 256)];
        else if (on < 384) v = (k < 256) ? w_ih[on * 256 + k] : 0.f;
        else               v = (k >= 256) ? w_hh[(on - 128) * 128 + (k - 256)] : 0.f;
        g_WBTh[idx] = __float2half_rn(v);
    }
    if (idx < 256 * 128) {  // [n][k]
        int n = idx >> 7, k = idx & 127;
        g_WETh[idx] = __float2half_rn((n < 128) ? W_ein[n * 128 + k] : W_eout[(n - 128) * 128 + k]);
        g_WQTh[idx] = __float2half_rn((n < 128) ? W_q1[n * 128 + k]  : W_q2[(n - 128) * 128 + k]);
    }
    if (idx < 512) {
        int j = idx >> 2, g = idx & 3;
        int on = (g == 0) ? j : (g == 1) ? 128 + j : (g == 2) ? 256 + j : 384 + j;
        g_biasBig[idx] = (on < 256) ? b_ih[on] + b_hh[on] : (on < 384) ? b_ih[on] : b_hh[on - 128];
    }
    if (idx < 256) {
        g_biasE[idx]  = (idx < 128) ? b_ein[idx] : b_eout[idx - 128];
        g_biasQ[idx]  = (idx < 128) ? b_q1[idx]  : b_q2[idx - 128];
        g_biasIO[idx] = (idx < 128) ? b_iah[idx] : b_oah[idx - 128];
    }
}

// ---------------- hidden -> fp16 ----------------
__global__ void cvt_hidden(const float* __restrict__ src) {
    int i = blockIdx.x * blockDim.x + threadIdx.x;   // one float4 per thread
    float4 v = reinterpret_cast<const float4*>(src)[i];
    reinterpret_cast<uint2*>(g_Hh)[i] = cvt_pack_f16(v);
}

// ---------------- fp16 warp-MMA GEMM ----------------
// CTA tile 128x128, chunks of K=32.
// MODE 0: E   = hidden @ WET^T              -> g_ETh (transposed, fp16) [cp.async]
// MODE 1: MSG = A[b] @ ET[b]^T              -> g_MSGh (fp16)            [reg-prefetch: X=A fp32]
// MODE 2: gates = [MSG|hidden] @ WBT^T, gate-interleaved; fused GRU -> g_H2 + g_H2h [cp.async]
// MODE 3: Q12 = H2 @ WQT^T                  -> g_Q12                    [cp.async]
#define LDS_ 40        // row stride in halfs (80B): conflict-free for STS/cp.async + ldmatrix
#define PLANE_H 5120   // halfs per plane (128 x 40)
#define STAGE_B (2 * PLANE_H * 2)  // bytes per stage (X plane + B plane)

template<int MODE>
__global__ void __launch_bounds__(256, 2) gemm_mma(const float* __restrict__ Xext) {
    __shared__ __align__(16) uint16_t smraw[2][2 * PLANE_H];  // 2 stages, 40KB
    uint32_t smb = (uint32_t)__cvta_generic_to_shared(&smraw[0][0]);

    int tid = threadIdx.x;
    int wid = tid >> 5, lane = tid & 31;
    int n0 = blockIdx.x * 128;
    int m0 = blockIdx.y * 128;
    int bz = blockIdx.z;

    const int K1 = (MODE == 1) ? 256 : (MODE == 2) ? 384 : 128;
    const int nc = K1 >> 5;

    const int wm0 = (wid & 3) * 32;
    const int wn0 = (wid >> 2) * 64;

    float acc[2][8][4];
#pragma unroll
    for (int i = 0; i < 2; i++)
#pragma unroll
        for (int j = 0; j < 8; j++)
#pragma unroll
            for (int c = 0; c < 4; c++) acc[i][j][c] = 0.f;

    // ldmatrix per-lane address components
    int am = lane & 15;
    int akh = (lane >> 4) << 3;
    int bnl = (lane & 7) + ((lane >> 4) << 3);
    int bkh = ((lane >> 3) & 1) << 3;

    auto compute = [&](uint32_t bufb) {
#pragma unroll
        for (int ks = 0; ks < 32; ks += 16) {
            uint32_t af[2][4];
#pragma unroll
            for (int i = 0; i < 2; i++) {
                uint32_t aoff = bufb + (uint32_t)((wm0 + i * 16 + am) * LDS_ + ks + akh) * 2;
                LDSM4(af[i], aoff);
            }
#pragma unroll
            for (int jp = 0; jp < 4; jp++) {
                uint32_t boff = bufb + (uint32_t)(PLANE_H + (wn0 + jp * 16 + bnl) * LDS_ + ks + bkh) * 2;
                uint32_t bf[4];
                LDSM4(bf, boff);
#pragma unroll
                for (int i = 0; i < 2; i++) {
#pragma unroll
                    for (int jj = 0; jj < 2; jj++) {
                        MMA_F16(acc[i][jp * 2 + jj], af[i], (bf + jj * 2));
                    }
                }
            }
        }
    };

    if constexpr (MODE == 1) {
        // ---- register-prefetch path: X = A (fp32, cvt), B = ETh (fp16) ----
        int r8 = tid >> 3, c4 = (tid & 7) * 4;
        uint2 xh[4], bh[4];
        const float* Xs = Xext + (size_t)bz * 131072;
        const __half* Bh = g_ETh + (size_t)bz * 65536;
        const int xcol0 = (n0 >= 128) ? 256 : 0;
        auto ldg_chunk = [&](int kt) {
#pragma unroll
            for (int p = 0; p < 4; p++)
                xh[p] = cvt_pack_f16(*reinterpret_cast<const float4*>(
                    Xs + (size_t)(m0 + p * 32 + r8) * 512 + kt + xcol0 + c4));
#pragma unroll
            for (int p = 0; p < 4; p++)
                bh[p] = *reinterpret_cast<const uint2*>(
                    Bh + (size_t)(n0 + p * 32 + r8) * 256 + kt + c4);
        };
        auto sts_chunk = [&](int pb) {
#pragma unroll
            for (int p = 0; p < 4; p++) {
                int off = (p * 32 + r8) * LDS_ + c4;
                *reinterpret_cast<uint2*>(&smraw[pb][off]) = xh[p];
                *reinterpret_cast<uint2*>(&smraw[pb][off + PLANE_H]) = bh[p];
            }
        };
        ldg_chunk(0);
        sts_chunk(0);
        __syncthreads();
        int pb = 0;
        for (int c = 0; c < nc; c++) {
            bool more = (c + 1 < nc);
            if (more) ldg_chunk((c + 1) * 32);
            compute(smb + (uint32_t)(pb * STAGE_B));
            if (more) sts_chunk(pb ^ 1);
            __syncthreads();
            pb ^= 1;
        }
    } else {
        // ---- cp.async path: both operands fp16 in GMEM ----
        auto issue = [&](int c) {
            int kt = c * 32;
            uint32_t sb = smb + (uint32_t)((c & 1) * STAGE_B);
            const __half* xs; int ldx;
            const __half* bs; int ldbv;
            if (MODE == 2) {
                if (kt < 256) { xs = g_MSGh + (size_t)m0 * 256 + kt; ldx = 256; }
                else          { xs = g_Hh + (size_t)m0 * 128 + (kt - 256); ldx = 128; }
                bs = g_WBTh + (size_t)n0 * 384 + kt; ldbv = 384;
            } else if (MODE == 0) {
                xs = g_Hh + (size_t)m0 * 128 + kt; ldx = 128;
                bs = g_WETh + (size_t)n0 * 128 + kt; ldbv = 128;
            } else {  // MODE 3
                xs = g_H2h + (size_t)m0 * 128 + kt; ldx = 128;
                bs = g_WQTh + (size_t)n0 * 128 + kt; ldbv = 128;
            }
#pragma unroll
            for (int i = 0; i < 2; i++) {
                int t = tid + 256 * i, r = t >> 2, sg = t & 3;
                cp_async16(sb + (uint32_t)(r * LDS_ + sg * 8) * 2, xs + (size_t)r * ldx + sg * 8);
            }
#pragma unroll
            for (int i = 0; i < 2; i++) {
                int t = tid + 256 * i, r = t >> 2, sg = t & 3;
                cp_async16(sb + (uint32_t)(PLANE_H + r * LDS_ + sg * 8) * 2, bs + (size_t)r * ldbv + sg * 8);
            }
            CP_COMMIT();
        };
        issue(0);
        for (int c = 0; c < nc; c++) {
            CP_WAIT0();
            __syncthreads();
            if (c + 1 < nc) issue(c + 1);
            compute(smb + (uint32_t)((c & 1) * STAGE_B));
        }
        __syncthreads();
    }

    // ---- epilogues ----
    int mrow = m0 + wm0 + (lane >> 2);
    int ncol = wn0 + (lane & 3) * 2;

    if (MODE == 2) {
        // Fused GRU on gate-interleaved preactivations.
        float* sh = reinterpret_cast<float*>(&smraw[0][0]);   // hidden tile [128][32]
        float* shH2 = sh + 4096;                              // H2 tile [128][32]
        int jc0 = n0 >> 2;
#pragma unroll
        for (int p = 0; p < 4; p++) {
            int r = p * 32 + (tid >> 3), cg = (tid & 7) * 4;
            *reinterpret_cast<float4*>(&sh[r * 32 + cg]) =
                *reinterpret_cast<const float4*>(Xext + (size_t)(m0 + r) * 128 + jc0 + cg);
        }
        __syncthreads();
#pragma unroll
        for (int i = 0; i < 2; i++) {
#pragma unroll
            for (int j = 0; j < 8; j++) {
                int n = n0 + ncol + 8 * j;
                float* cc = acc[i][j];
                float g0 = cc[0] + g_biasBig[n];
                float g1 = cc[1] + g_biasBig[n + 1];
                float g2 = cc[2] + g_biasBig[n];
                float g3 = cc[3] + g_biasBig[n + 1];
                float s0 = (lane & 1) ? g0 : g2;
                float s1 = (lane & 1) ? g1 : g3;
                float r0 = __shfl_xor_sync(0xFFFFFFFFu, s0, 1);
                float r1 = __shfl_xor_sync(0xFFFFFFFFu, s1, 1);
                float a0, a1, a2, a3;
                if (lane & 1) { a0 = r0; a1 = r1; a2 = g2; a3 = g3; }
                else          { a0 = g0; a1 = g1; a2 = r0; a3 = r1; }
                int jl = (ncol + 8 * j) >> 2;
                int rl = wm0 + (lane >> 2) + 16 * i + ((lane & 1) ? 8 : 0);
                float hv = sh[rl * 32 + jl];
                float rg = 1.f / (1.f + expf(-a0));
                float zg = 1.f / (1.f + expf(-a1));
                float ng = tanhf(a2 + rg * a3);
                shH2[rl * 32 + jl] = hv - zg * (hv - ng);
            }
        }
        __syncthreads();
#pragma unroll
        for (int p = 0; p < 4; p++) {
            int r = p * 32 + (tid >> 3), cg = (tid & 7) * 4;
            float4 v = *reinterpret_cast<float4*>(&shH2[r * 32 + cg]);
            *reinterpret_cast<float4*>(g_H2 + (size_t)(m0 + r) * 128 + jc0 + cg) = v;
            *reinterpret_cast<uint2*>(g_H2h + (size_t)(m0 + r) * 128 + jc0 + cg) = cvt_pack_f16(v);
        }
    } else if (MODE == 0) {
        int b = mrow >> 8, s = mrow & 255;
        __half* o = g_ETh + (size_t)b * 65536;
#pragma unroll
        for (int i = 0; i < 2; i++) {
            int s0 = s + i * 16;
#pragma unroll
            for (int j = 0; j < 8; j++) {
                int n = n0 + ncol + j * 8;
                float* cc = acc[i][j];
                o[(size_t)n * 256 + s0]           = __float2half_rn(cc[0] + g_biasE[n]);
                o[(size_t)(n + 1) * 256 + s0]     = __float2half_rn(cc[1] + g_biasE[n + 1]);
                o[(size_t)n * 256 + s0 + 8]       = __float2half_rn(cc[2] + g_biasE[n]);
                o[(size_t)(n + 1) * 256 + s0 + 8] = __float2half_rn(cc[3] + g_biasE[n + 1]);
            }
        }
    } else if (MODE == 1) {
        size_t rbase = (size_t)bz * 256 + mrow;
#pragma unroll
        for (int i = 0; i < 2; i++) {
            __half* o0 = g_MSGh + (rbase + i * 16) * 256;
            __half* o1 = o0 + 8 * 256;
#pragma unroll
            for (int j = 0; j < 8; j++) {
                int n = n0 + ncol + j * 8;
                float* cc = acc[i][j];
                *reinterpret_cast<__half2*>(o0 + n) =
                    __floats2half2_rn(cc[0] + g_biasIO[n], cc[1] + g_biasIO[n + 1]);
                *reinterpret_cast<__half2*>(o1 + n) =
                    __floats2half2_rn(cc[2] + g_biasIO[n], cc[3] + g_biasIO[n + 1]);
            }
        }
    } else {  // MODE 3
        size_t rbase = (size_t)mrow;
#pragma unroll
        for (int i = 0; i < 2; i++) {
            float* o0 = g_Q12 + (rbase + i * 16) * 256;
            float* o1 = o0 + 8 * 256;
#pragma unroll
            for (int j = 0; j < 8; j++) {
                int n = n0 + ncol + j * 8;
                float* cc = acc[i][j];
                float2 v0 = make_float2(cc[0] + g_biasQ[n], cc[1] + g_biasQ[n + 1]);
                float2 v1 = make_float2(cc[2] + g_biasQ[n], cc[3] + g_biasQ[n + 1]);
                *reinterpret_cast<float2*>(o0 + n) = v0;
                *reinterpret_cast<float2*>(o1 + n) = v1;
            }
        }
    }
}

// ---------------- nvalid + ht1 gather + q0 GEMV ----------------
__global__ void q0_kernel(const int* __restrict__ mask,
                          const float* __restrict__ W_q0, const float* __restrict__ b_q0) {
    __shared__ int ired[128];
    __shared__ float ht[128];
    int b = blockIdx.x, t = threadIdx.x;
    ired[t] = mask[b * 256 + t] + mask[b * 256 + 128 + t];
    __syncthreads();
    for (int off = 64; off; off >>= 1) {
        if (t < off) ired[t] += ired[t + off];
        __syncthreads();
    }
    int nv = ired[0];
    int li = nv - 1;
    ht[t] = g_H2[((size_t)b * 256 + li) * 128 + t];
    __syncthreads();
    float acc = 0.f;
#pragma unroll 8
    for (int k = 0; k < 128; k++) acc += ht[k] * W_q0[t * 128 + k];
    g_q0v[b * 128 + t] = acc + b_q0[t];
    if (t == 0) g_nvalid[b] = nv;
}

// ---------------- collapsed attention readout ----------------
__global__ void attn_kernel(float* __restrict__ out) {
    __shared__ float q0s[128];
    __shared__ float sc[8][256];
    __shared__ float red[256];
    int b = blockIdx.x, t = threadIdx.x;
    const float* Q = g_Q12 + (size_t)b * 256 * 256;
    if (t < 128) q0s[t] = g_q0v[b * 128 + t];
    __syncthreads();
    for (int e = t; e < 2048; e += 256) {
        int h = e >> 8, j = e & 255;
        const float* q1 = Q + j * 256 + h * 16;
        float s = 0.f;
#pragma unroll
        for (int d = 0; d < 16; d++) s += q0s[h * 16 + d] * q1[d];
        sc[h][j] = 1.f / (1.f + expf(-s));
    }
    __syncthreads();
    {
        int w = t >> 5, lane = t & 31;
        float sum = 0.f;
        for (int j = lane; j < 256; j += 32) {
            float e = expf(sc[w][j]);
            sc[w][j] = e;
            sum += e;
        }
#pragma unroll
        for (int o = 16; o; o >>= 1) sum += __shfl_xor_sync(0xFFFFFFFFu, sum, o);
        float inv = 1.f / sum;
        for (int j = lane; j < 256; j += 32) sc[w][j] *= inv;
    }
    __syncthreads();
    {
        int j = t;
        float e[8], s = 0.f;
#pragma unroll
        for (int h = 0; h < 8; h++) { e[h] = expf(2.f * sc[h][j]); s += e[h]; }
        float inv = 1.f / s;
#pragma unroll
        for (int h = 0; h < 8; h++) sc[h][j] = e[h] * inv;
    }
    __syncthreads();
    {
        int o = t & 127, half = t >> 7;
        int h = o >> 4, d = o & 15;
        float acc = 0.f;
        int j0 = half * 128;
        for (int j = j0; j < j0 + 128; j++)
            acc += sc[h][j] * Q[j * 256 + 128 + h * 16 + d];
        red[t] = acc;
    }
    __syncthreads();
    if (t < 128) {
        float y = red[t] + red[t + 128];
        out[b * 128 + t] = (float)g_nvalid[b] * y;
    }
}

// ---------------- launch ----------------
extern "C" void kernel_launch(void* const* d_in, const int* in_sizes, int n_in,
                              void* d_out, int out_size) {
    const float* A      = (const float*)d_in[0];
    const float* hidden = (const float*)d_in[1];
    const int*   mask   = (const int*)d_in[2];
    const float* w_ih   = (const float*)d_in[3];
    const float* w_hh   = (const float*)d_in[4];
    const float* b_ih   = (const float*)d_in[5];
    const float* b_hh   = (const float*)d_in[6];
    const float* b_iah  = (const float*)d_in[7];
    const float* b_oah  = (const float*)d_in[8];
    const float* W_ein  = (const float*)d_in[9];
    const float* b_ein  = (const float*)d_in[10];
    const float* W_eout = (const float*)d_in[11];
    const float* b_eout = (const float*)d_in[12];
    const float* W_q0   = (const float*)d_in[13];
    const float* b_q0   = (const float*)d_in[14];
    const float* W_q1   = (const float*)d_in[15];
    const float* b_q1   = (const float*)d_in[16];
    const float* W_q2   = (const float*)d_in[17];
    const float* b_q2   = (const float*)d_in[18];
    float* out = (float*)d_out;

    // 0) weight prep + hidden fp16
    prep_kernel<<<768, 256>>>(w_ih, w_hh, b_ih, b_hh, W_ein, b_ein, W_eout, b_eout,
                              b_iah, b_oah, W_q1, b_q1, W_q2, b_q2);
    cvt_hidden<<<4096, 256>>>(hidden);
    // 1) E^T -> g_ETh (fp16)
    gemm_mma<0><<<dim3(2, 256, 1), 256>>>(hidden);
    // 2) MSG = A @ E -> g_MSGh (fp16)
    gemm_mma<1><<<dim3(2, 2, 128), 256>>>(A);
    // 3) gates + fused GRU -> g_H2 / g_H2h
    gemm_mma<2><<<dim3(4, 256, 1), 256>>>(hidden);
    // 4) nvalid, ht1, q0
    q0_kernel<<<128, 128>>>(mask, W_q0, b_q0);
    // 5) Q12 = H2 @ WQT^T -> g_Q12
    gemm_mma<3><<<dim3(2, 256, 1), 256>>>(nullptr);
    // 6) collapsed attention + readout
    attn_kernel<<<128, 256>>>(out);
}

// round 16
// speedup vs baseline: 1.1788x; 1.0398x over previous
#include <cuda_runtime.h>
#include <cuda_fp16.h>
#include <math.h>
#include <stdint.h>

// ---------------- problem constants ----------------
#define B_ 128
#define S_ 256
#define H_ 128

// ---------------- device scratch (allocation-free) ----------------
__device__ __align__(16) __half g_ETh[B_ * 256 * 256];   // [b][n][s] E^T fp16 (B-op of MSG)
__device__ __align__(16) __half g_MSGh[B_ * S_ * 256];   // [m][256] fp16
__device__ __align__(16) __half g_Hh[B_ * S_ * H_];      // fp16 copy of hidden
__device__ __align__(16) __half g_H2h[B_ * S_ * H_];     // fp16 copy of new hidden
__device__ float  g_H2[B_ * S_ * H_];                    // new hidden (fp32, for q0)
__device__ float  g_Q12[B_ * S_ * 256];                  // [m][256] q1|q2
__device__ __align__(16) __half g_WETh[256 * 128];       // [n][k]
__device__ __align__(16) __half g_WQTh[256 * 128];       // [n][k]
__device__ __align__(16) __half g_WBTh[512 * 384];       // [n'][k], gate-interleaved n' = 4*j + g
__device__ float  g_biasE[256];
__device__ float  g_biasQ[256];
__device__ float  g_biasIO[256];
__device__ float  g_biasBig[512];                        // gate-interleaved
__device__ float  g_q0v[B_ * H_];
__device__ int    g_nvalid[B_];

// ---------------- helpers ----------------
__device__ __forceinline__ uint2 cvt_pack_f16(float4 v) {
    __half2 a = __floats2half2_rn(v.x, v.y);
    __half2 b = __floats2half2_rn(v.z, v.w);
    return make_uint2(*reinterpret_cast<uint32_t*>(&a), *reinterpret_cast<uint32_t*>(&b));
}

__device__ __forceinline__ void cp_async16(uint32_t dst, const void* src) {
    asm volatile("cp.async.cg.shared.global [%0], [%1], 16;" :: "r"(dst), "l"(src));
}
#define CP_COMMIT() asm volatile("cp.async.commit_group;" ::: "memory")
#define CP_WAIT0()  asm volatile("cp.async.wait_group 0;" ::: "memory")
#define CP_WAIT1()  asm volatile("cp.async.wait_group 1;" ::: "memory")

#define LDSM4(r, a) \
    asm volatile("ldmatrix.sync.aligned.m8n8.x4.shared.b16 {%0,%1,%2,%3}, [%4];" \
                 : "=r"((r)[0]), "=r"((r)[1]), "=r"((r)[2]), "=r"((r)[3]) : "r"(a))

#define MMA_F16(c, a, b) \
    asm volatile("mma.sync.aligned.m16n8k16.row.col.f32.f16.f16.f32 " \
                 "{%0,%1,%2,%3}, {%4,%5,%6,%7}, {%8,%9}, {%0,%1,%2,%3};" \
                 : "+f"((c)[0]), "+f"((c)[1]), "+f"((c)[2]), "+f"((c)[3]) \
                 : "r"((a)[0]), "r"((a)[1]), "r"((a)[2]), "r"((a)[3]), \
                   "r"((b)[0]), "r"((b)[1]))

// ---------------- weight prep (fp16 weights; WBT gate-interleaved) ----------------
__global__ void prep_kernel(const float* __restrict__ w_ih, const float* __restrict__ w_hh,
                            const float* __restrict__ b_ih, const float* __restrict__ b_hh,
                            const float* __restrict__ W_ein, const float* __restrict__ b_ein,
                            const float* __restrict__ W_eout, const float* __restrict__ b_eout,
                            const float* __restrict__ b_iah, const float* __restrict__ b_oah,
                            const float* __restrict__ W_q1, const float* __restrict__ b_q1,
                            const float* __restrict__ W_q2, const float* __restrict__ b_q2) {
    int idx = blockIdx.x * blockDim.x + threadIdx.x;
    if (idx < 512 * 384) {  // g_WBTh [n'][k], n' = 4*j + g
        int np = idx / 384, k = idx - np * 384;
        int j = np >> 2, g = np & 3;
        int on = (g == 0) ? j : (g == 1) ? 128 + j : (g == 2) ? 256 + j : 384 + j;
        float v;
        if (on < 256)      v = (k < 256) ? w_ih[on * 256 + k] : w_hh[on * 128 + (k - 256)];
        else if (on < 384) v = (k < 256) ? w_ih[on * 256 + k] : 0.f;
        else               v = (k >= 256) ? w_hh[(on - 128) * 128 + (k - 256)] : 0.f;
        g_WBTh[idx] = __float2half_rn(v);
    }
    if (idx < 256 * 128) {  // [n][k]
        int n = idx >> 7, k = idx & 127;
        g_WETh[idx] = __float2half_rn((n < 128) ? W_ein[n * 128 + k] : W_eout[(n - 128) * 128 + k]);
        g_WQTh[idx] = __float2half_rn((n < 128) ? W_q1[n * 128 + k]  : W_q2[(n - 128) * 128 + k]);
    }
    if (idx < 512) {
        int j = idx >> 2, g = idx & 3;
        int on = (g == 0) ? j : (g == 1) ? 128 + j : (g == 2) ? 256 + j : 384 + j;
        g_biasBig[idx] = (on < 256) ? b_ih[on] + b_hh[on] : (on < 384) ? b_ih[on] : b_hh[on - 128];
    }
    if (idx < 256) {
        g_biasE[idx]  = (idx < 128) ? b_ein[idx] : b_eout[idx - 128];
        g_biasQ[idx]  = (idx < 128) ? b_q1[idx]  : b_q2[idx - 128];
        g_biasIO[idx] = (idx < 128) ? b_iah[idx] : b_oah[idx - 128];
    }
}

// ---------------- hidden -> fp16 ----------------
__global__ void cvt_hidden(const float* __restrict__ src) {
    int i = blockIdx.x * blockDim.x + threadIdx.x;
    float4 v = reinterpret_cast<const float4*>(src)[i];
    reinterpret_cast<uint2*>(g_Hh)[i] = cvt_pack_f16(v);
}

// ---------------- fp16 warp-MMA GEMM ----------------
// CTA tile 128x128, chunks of K=32.
// MODE 0: E   = hidden @ WET^T              -> g_ETh (transposed, fp16) [3-stage cp.async]
// MODE 1: MSG = A[b] @ ET[b]^T              -> g_MSGh (fp16) [X reg-prefetch, B cp.async]
// MODE 2: gates + fused GRU                 -> g_H2 + g_H2h  [3-stage cp.async]
// MODE 3: Q12 = H2 @ WQT^T                  -> g_Q12         [3-stage cp.async]
#define LDS_ 40        // row stride in halfs (80B): conflict-free for STS/cp.async + ldmatrix
#define PLANE_H 5120   // halfs per plane (128 x 40)
#define STAGE_B (2 * PLANE_H * 2)      // 20480 bytes per stage
#define SMEM3 (3 * STAGE_B)            // 61440 (modes 0/2/3)
#define SMEM2 (2 * STAGE_B)            // 40960 (mode 1)

template<int MODE>
__global__ void __launch_bounds__(256, 2) gemm_mma(const float* __restrict__ Xext) {
    extern __shared__ __align__(16) uint16_t smraw[];
    uint32_t smb = (uint32_t)__cvta_generic_to_shared(&smraw[0]);

    int tid = threadIdx.x;
    int wid = tid >> 5, lane = tid & 31;
    int n0 = blockIdx.x * 128;
    int m0 = blockIdx.y * 128;
    int bz = blockIdx.z;

    const int K1 = (MODE == 1) ? 256 : (MODE == 2) ? 384 : 128;
    const int nc = K1 >> 5;

    const int wm0 = (wid & 3) * 32;
    const int wn0 = (wid >> 2) * 64;

    float acc[2][8][4];
#pragma unroll
    for (int i = 0; i < 2; i++)
#pragma unroll
        for (int j = 0; j < 8; j++)
#pragma unroll
            for (int c = 0; c < 4; c++) acc[i][j][c] = 0.f;

    // ldmatrix per-lane address components
    int am = lane & 15;
    int akh = (lane >> 4) << 3;
    int bnl = (lane & 7) + ((lane >> 4) << 3);
    int bkh = ((lane >> 3) & 1) << 3;

    auto compute = [&](uint32_t bufb) {
#pragma unroll
        for (int ks = 0; ks < 32; ks += 16) {
            uint32_t af[2][4];
#pragma unroll
            for (int i = 0; i < 2; i++) {
                uint32_t aoff = bufb + (uint32_t)((wm0 + i * 16 + am) * LDS_ + ks + akh) * 2;
                LDSM4(af[i], aoff);
            }
#pragma unroll
            for (int jp = 0; jp < 4; jp++) {
                uint32_t boff = bufb + (uint32_t)(PLANE_H + (wn0 + jp * 16 + bnl) * LDS_ + ks + bkh) * 2;
                uint32_t bf[4];
                LDSM4(bf, boff);
#pragma unroll
                for (int i = 0; i < 2; i++) {
#pragma unroll
                    for (int jj = 0; jj < 2; jj++) {
                        MMA_F16(acc[i][jp * 2 + jj], af[i], (bf + jj * 2));
                    }
                }
            }
        }
    };

    if constexpr (MODE == 1) {
        // ---- X = A (fp32, reg-prefetch + cvt + STS); B = ETh (fp16, cp.async) ----
        int r8 = tid >> 3, c4 = (tid & 7) * 4;
        uint2 xh[4];
        const float* Xs = Xext + (size_t)bz * 131072;
        const __half* Bh = g_ETh + (size_t)bz * 65536;
        const int xcol0 = (n0 >= 128) ? 256 : 0;
        auto ldgX = [&](int kt) {
#pragma unroll
            for (int p = 0; p < 4; p++)
                xh[p] = cvt_pack_f16(*reinterpret_cast<const float4*>(
                    Xs + (size_t)(m0 + p * 32 + r8) * 512 + kt + xcol0 + c4));
        };
        auto stsX = [&](int pb) {
            uint32_t sb = smb + (uint32_t)(pb * STAGE_B);
#pragma unroll
            for (int p = 0; p < 4; p++)
                *reinterpret_cast<uint2*>(&smraw[(size_t)pb * (2 * PLANE_H) +
                                                 (p * 32 + r8) * LDS_ + c4]) = xh[p];
            (void)sb;
        };
        auto cpB = [&](int kt, int pb) {
            uint32_t sb = smb + (uint32_t)(pb * STAGE_B);
#pragma unroll
            for (int i = 0; i < 2; i++) {
                int t = tid + 256 * i, r = t >> 2, sg = t & 3;
                cp_async16(sb + (uint32_t)(PLANE_H + r * LDS_ + sg * 8) * 2,
                           Bh + (size_t)(n0 + r) * 256 + kt + sg * 8);
            }
            CP_COMMIT();
        };
        // prologue
        cpB(0, 0);
        ldgX(0);
        stsX(0);
        int pb = 0;
        for (int c = 0; c < nc; c++) {
            bool more = (c + 1 < nc);
            if (more) ldgX((c + 1) * 32);
            CP_WAIT0();
            __syncthreads();
            if (more) cpB((c + 1) * 32, pb ^ 1);
            compute(smb + (uint32_t)(pb * STAGE_B));
            if (more) stsX(pb ^ 1);
            pb ^= 1;
        }
    } else {
        // ---- 3-stage cp.async path: both operands fp16 in GMEM ----
        auto issue = [&](int c) {
            int kt = c * 32;
            uint32_t sb = smb + (uint32_t)((c % 3) * STAGE_B);
            const __half* xs; int ldx;
            const __half* bs; int ldbv;
            if (MODE == 2) {
                if (kt < 256) { xs = g_MSGh + (size_t)m0 * 256 + kt; ldx = 256; }
                else          { xs = g_Hh + (size_t)m0 * 128 + (kt - 256); ldx = 128; }
                bs = g_WBTh + (size_t)n0 * 384 + kt; ldbv = 384;
            } else if (MODE == 0) {
                xs = g_Hh + (size_t)m0 * 128 + kt; ldx = 128;
                bs = g_WETh + (size_t)n0 * 128 + kt; ldbv = 128;
            } else {  // MODE 3
                xs = g_H2h + (size_t)m0 * 128 + kt; ldx = 128;
                bs = g_WQTh + (size_t)n0 * 128 + kt; ldbv = 128;
            }
#pragma unroll
            for (int i = 0; i < 2; i++) {
                int t = tid + 256 * i, r = t >> 2, sg = t & 3;
                cp_async16(sb + (uint32_t)(r * LDS_ + sg * 8) * 2, xs + (size_t)r * ldx + sg * 8);
            }
#pragma unroll
            for (int i = 0; i < 2; i++) {
                int t = tid + 256 * i, r = t >> 2, sg = t & 3;
                cp_async16(sb + (uint32_t)(PLANE_H + r * LDS_ + sg * 8) * 2, bs + (size_t)r * ldbv + sg * 8);
            }
            CP_COMMIT();
        };
        issue(0);
        if (nc > 1) issue(1);
        for (int c = 0; c < nc; c++) {
            if (c + 1 < nc) CP_WAIT1(); else CP_WAIT0();
            __syncthreads();
            if (c + 2 < nc) issue(c + 2);
            compute(smb + (uint32_t)((c % 3) * STAGE_B));
        }
        __syncthreads();
    }

    // ---- epilogues ----
    int mrow = m0 + wm0 + (lane >> 2);
    int ncol = wn0 + (lane & 3) * 2;

    if (MODE == 2) {
        // Fused GRU on gate-interleaved preactivations.
        float* sh = reinterpret_cast<float*>(&smraw[0]);   // hidden tile [128][32]
        float* shH2 = sh + 4096;                           // H2 tile [128][32]
        int jc0 = n0 >> 2;
#pragma unroll
        for (int p = 0; p < 4; p++) {
            int r = p * 32 + (tid >> 3), cg = (tid & 7) * 4;
            *reinterpret_cast<float4*>(&sh[r * 32 + cg]) =
                *reinterpret_cast<const float4*>(Xext + (size_t)(m0 + r) * 128 + jc0 + cg);
        }
        __syncthreads();
#pragma unroll
        for (int i = 0; i < 2; i++) {
#pragma unroll
            for (int j = 0; j < 8; j++) {
                int n = n0 + ncol + 8 * j;
                float* cc = acc[i][j];
                float g0 = cc[0] + g_biasBig[n];
                float g1 = cc[1] + g_biasBig[n + 1];
                float g2 = cc[2] + g_biasBig[n];
                float g3 = cc[3] + g_biasBig[n + 1];
                float s0 = (lane & 1) ? g0 : g2;
                float s1 = (lane & 1) ? g1 : g3;
                float r0 = __shfl_xor_sync(0xFFFFFFFFu, s0, 1);
                float r1 = __shfl_xor_sync(0xFFFFFFFFu, s1, 1);
                float a0, a1, a2, a3;
                if (lane & 1) { a0 = r0; a1 = r1; a2 = g2; a3 = g3; }
                else          { a0 = g0; a1 = g1; a2 = r0; a3 = r1; }
                int jl = (ncol + 8 * j) >> 2;
                int rl = wm0 + (lane >> 2) + 16 * i + ((lane & 1) ? 8 : 0);
                float hv = sh[rl * 32 + jl];
                float rg = 1.f / (1.f + expf(-a0));
                float zg = 1.f / (1.f + expf(-a1));
                float ng = tanhf(a2 + rg * a3);
                shH2[rl * 32 + jl] = hv - zg * (hv - ng);
            }
        }
        __syncthreads();
#pragma unroll
        for (int p = 0; p < 4; p++) {
            int r = p * 32 + (tid >> 3), cg = (tid & 7) * 4;
            float4 v = *reinterpret_cast<float4*>(&shH2[r * 32 + cg]);
            *reinterpret_cast<float4*>(g_H2 + (size_t)(m0 + r) * 128 + jc0 + cg) = v;
            *reinterpret_cast<uint2*>(g_H2h + (size_t)(m0 + r) * 128 + jc0 + cg) = cvt_pack_f16(v);
        }
    } else if (MODE == 0) {
        int b = mrow >> 8, s = mrow & 255;
        __half* o = g_ETh + (size_t)b * 65536;
#pragma unroll
        for (int i = 0; i < 2; i++) {
            int s0 = s + i * 16;
#pragma unroll
            for (int j = 0; j < 8; j++) {
                int n = n0 + ncol + j * 8;
                float* cc = acc[i][j];
                o[(size_t)n * 256 + s0]           = __float2half_rn(cc[0] + g_biasE[n]);
                o[(size_t)(n + 1) * 256 + s0]     = __float2half_rn(cc[1] + g_biasE[n + 1]);
                o[(size_t)n * 256 + s0 + 8]       = __float2half_rn(cc[2] + g_biasE[n]);
                o[(size_t)(n + 1) * 256 + s0 + 8] = __float2half_rn(cc[3] + g_biasE[n + 1]);
            }
        }
    } else if (MODE == 1) {
        size_t rbase = (size_t)bz * 256 + mrow;
#pragma unroll
        for (int i = 0; i < 2; i++) {
            __half* o0 = g_MSGh + (rbase + i * 16) * 256;
            __half* o1 = o0 + 8 * 256;
#pragma unroll
            for (int j = 0; j < 8; j++) {
                int n = n0 + ncol + j * 8;
                float* cc = acc[i][j];
                *reinterpret_cast<__half2*>(o0 + n) =
                    __floats2half2_rn(cc[0] + g_biasIO[n], cc[1] + g_biasIO[n + 1]);
                *reinterpret_cast<__half2*>(o1 + n) =
                    __floats2half2_rn(cc[2] + g_biasIO[n], cc[3] + g_biasIO[n + 1]);
            }
        }
    } else {  // MODE 3
        size_t rbase = (size_t)mrow;
#pragma unroll
        for (int i = 0; i < 2; i++) {
            float* o0 = g_Q12 + (rbase + i * 16) * 256;
            float* o1 = o0 + 8 * 256;
#pragma unroll
            for (int j = 0; j < 8; j++) {
                int n = n0 + ncol + j * 8;
                float* cc = acc[i][j];
                float2 v0 = make_float2(cc[0] + g_biasQ[n], cc[1] + g_biasQ[n + 1]);
                float2 v1 = make_float2(cc[2] + g_biasQ[n], cc[3] + g_biasQ[n + 1]);
                *reinterpret_cast<float2*>(o0 + n) = v0;
                *reinterpret_cast<float2*>(o1 + n) = v1;
            }
        }
    }
}

// ---------------- nvalid + ht1 gather + q0 GEMV ----------------
__global__ void q0_kernel(const int* __restrict__ mask,
                          const float* __restrict__ W_q0, const float* __restrict__ b_q0) {
    __shared__ int ired[128];
    __shared__ float ht[128];
    int b = blockIdx.x, t = threadIdx.x;
    ired[t] = mask[b * 256 + t] + mask[b * 256 + 128 + t];
    __syncthreads();
    for (int off = 64; off; off >>= 1) {
        if (t < off) ired[t] += ired[t + off];
        __syncthreads();
    }
    int nv = ired[0];
    int li = nv - 1;
    ht[t] = g_H2[((size_t)b * 256 + li) * 128 + t];
    __syncthreads();
    float acc = 0.f;
#pragma unroll 8
    for (int k = 0; k < 128; k++) acc += ht[k] * W_q0[t * 128 + k];
    g_q0v[b * 128 + t] = acc + b_q0[t];
    if (t == 0) g_nvalid[b] = nv;
}

// ---------------- collapsed attention readout (512 threads) ----------------
__global__ void __launch_bounds__(512) attn_kernel(float* __restrict__ out) {
    __shared__ float q0s[128];
    __shared__ float sc[8][256];
    __shared__ float red[512];
    int b = blockIdx.x, t = threadIdx.x;
    const float* Q = g_Q12 + (size_t)b * 256 * 256;
    if (t < 128) q0s[t] = g_q0v[b * 128 + t];
    __syncthreads();
    // scores + sigmoid (4 iters/thread)
    for (int e = t; e < 2048; e += 512) {
        int h = e >> 8, j = e & 255;
        const float* q1 = Q + j * 256 + h * 16;
        float s = 0.f;
#pragma unroll
        for (int d = 0; d < 16; d++) s += q0s[h * 16 + d] * q1[d];
        sc[h][j] = 1.f / (1.f + expf(-s));
    }
    __syncthreads();
    // per-head softmax over j (warps 0-7)
    {
        int w = t >> 5, lane = t & 31;
        if (w < 8) {
            float sum = 0.f;
            for (int j = lane; j < 256; j += 32) {
                float e = expf(sc[w][j]);
                sc[w][j] = e;
                sum += e;
            }
#pragma unroll
            for (int o = 16; o; o >>= 1) sum += __shfl_xor_sync(0xFFFFFFFFu, sum, o);
            float inv = 1.f / sum;
            for (int j = lane; j < 256; j += 32) sc[w][j] *= inv;
        }
    }
    __syncthreads();
    // per-j softmax over heads (threads 0-255)
    if (t < 256) {
        int j = t;
        float e[8], s = 0.f;
#pragma unroll
        for (int h = 0; h < 8; h++) { e[h] = expf(2.f * sc[h][j]); s += e[h]; }
        float inv = 1.f / s;
#pragma unroll
        for (int h = 0; h < 8; h++) sc[h][j] = e[h] * inv;
    }
    __syncthreads();
    // y[h,d] = sum_j g[h,j] * q2[j, h*16+d]; 4-way split of j
    {
        int o = t & 127, quarter = t >> 7;
        int h = o >> 4, d = o & 15;
        float acc = 0.f;
        int j0 = quarter * 64;
        for (int j = j0; j < j0 + 64; j++)
            acc += sc[h][j] * Q[j * 256 + 128 + h * 16 + d];
        red[t] = acc;
    }
    __syncthreads();
    if (t < 128) {
        float y = red[t] + red[t + 128] + red[t + 256] + red[t + 384];
        out[b * 128 + t] = (float)g_nvalid[b] * y;
    }
}

// ---------------- launch ----------------
extern "C" void kernel_launch(void* const* d_in, const int* in_sizes, int n_in,
                              void* d_out, int out_size) {
    const float* A      = (const float*)d_in[0];
    const float* hidden = (const float*)d_in[1];
    const int*   mask   = (const int*)d_in[2];
    const float* w_ih   = (const float*)d_in[3];
    const float* w_hh   = (const float*)d_in[4];
    const float* b_ih   = (const float*)d_in[5];
    const float* b_hh   = (const float*)d_in[6];
    const float* b_iah  = (const float*)d_in[7];
    const float* b_oah  = (const float*)d_in[8];
    const float* W_ein  = (const float*)d_in[9];
    const float* b_ein  = (const float*)d_in[10];
    const float* W_eout = (const float*)d_in[11];
    const float* b_eout = (const float*)d_in[12];
    const float* W_q0   = (const float*)d_in[13];
    const float* b_q0   = (const float*)d_in[14];
    const float* W_q1   = (const float*)d_in[15];
    const float* b_q1   = (const float*)d_in[16];
    const float* W_q2   = (const float*)d_in[17];
    const float* b_q2   = (const float*)d_in[18];
    float* out = (float*)d_out;

    static bool attr_done = false;
    if (!attr_done) {
        cudaFuncSetAttribute(gemm_mma<0>, cudaFuncAttributeMaxDynamicSharedMemorySize, SMEM3);
        cudaFuncSetAttribute(gemm_mma<1>, cudaFuncAttributeMaxDynamicSharedMemorySize, SMEM2);
        cudaFuncSetAttribute(gemm_mma<2>, cudaFuncAttributeMaxDynamicSharedMemorySize, SMEM3);
        cudaFuncSetAttribute(gemm_mma<3>, cudaFuncAttributeMaxDynamicSharedMemorySize, SMEM3);
        attr_done = true;
    }

    // 0) weight prep + hidden fp16
    prep_kernel<<<768, 256>>>(w_ih, w_hh, b_ih, b_hh, W_ein, b_ein, W_eout, b_eout,
                              b_iah, b_oah, W_q1, b_q1, W_q2, b_q2);
    cvt_hidden<<<4096, 256>>>(hidden);
    // 1) E^T -> g_ETh (fp16)
    gemm_mma<0><<<dim3(2, 256, 1), 256, SMEM3>>>(hidden);
    // 2) MSG = A @ E -> g_MSGh (fp16)
    gemm_mma<1><<<dim3(2, 2, 128), 256, SMEM2>>>(A);
    // 3) gates + fused GRU -> g_H2 / g_H2h
    gemm_mma<2><<<dim3(4, 256, 1), 256, SMEM3>>>(hidden);
    // 4) nvalid, ht1, q0
    q0_kernel<<<128, 128>>>(mask, W_q0, b_q0);
    // 5) Q12 = H2 @ WQT^T -> g_Q12
    gemm_mma<3><<<dim3(2, 256, 1), 256, SMEM3>>>(nullptr);
    // 6) collapsed attention + readout
    attn_kernel<<<128, 512>>>(out);
}

// round 17
// speedup vs baseline: 1.3040x; 1.1062x over previous
#include <cuda_runtime.h>
#include <cuda_fp16.h>
#include <math.h>
#include <stdint.h>

// ---------------- problem constants ----------------
#define B_ 128
#define S_ 256
#define H_ 128

// ---------------- device scratch (allocation-free) ----------------
__device__ __align__(16) __half g_ETh[B_ * 256 * 256];   // [b][n][s] E^T fp16 (B-op of MSG)
__device__ __align__(16) __half g_MSGh[B_ * S_ * 256];   // [m][256] fp16
__device__ __align__(16) __half g_Hh[B_ * S_ * H_];      // fp16 copy of hidden
__device__ __align__(16) __half g_H2h[B_ * S_ * H_];     // new hidden (fp16)
__device__ __align__(16) __half g_WETh[256 * 128];       // [n][k]
__device__ __align__(16) __half g_WBTh[512 * 384];       // [n'][k], gate-interleaved n' = 4*j + g
__device__ float  g_biasE[256];
__device__ float  g_biasIO[256];
__device__ float  g_biasBig[512];                        // gate-interleaved
__device__ float  g_q0v[B_ * H_];
__device__ int    g_nvalid[B_];

// ---------------- helpers ----------------
__device__ __forceinline__ uint2 cvt_pack_f16(float4 v) {
    __half2 a = __floats2half2_rn(v.x, v.y);
    __half2 b = __floats2half2_rn(v.z, v.w);
    return make_uint2(*reinterpret_cast<uint32_t*>(&a), *reinterpret_cast<uint32_t*>(&b));
}

__device__ __forceinline__ void cp_async16(uint32_t dst, const void* src) {
    asm volatile("cp.async.cg.shared.global [%0], [%1], 16;" :: "r"(dst), "l"(src));
}
#define CP_COMMIT() asm volatile("cp.async.commit_group;" ::: "memory")
#define CP_WAIT0()  asm volatile("cp.async.wait_group 0;" ::: "memory")
#define CP_WAIT1()  asm volatile("cp.async.wait_group 1;" ::: "memory")

#define LDSM4(r, a) \
    asm volatile("ldmatrix.sync.aligned.m8n8.x4.shared.b16 {%0,%1,%2,%3}, [%4];" \
                 : "=r"((r)[0]), "=r"((r)[1]), "=r"((r)[2]), "=r"((r)[3]) : "r"(a))

#define MMA_F16(c, a, b) \
    asm volatile("mma.sync.aligned.m16n8k16.row.col.f32.f16.f16.f32 " \
                 "{%0,%1,%2,%3}, {%4,%5,%6,%7}, {%8,%9}, {%0,%1,%2,%3};" \
                 : "+f"((c)[0]), "+f"((c)[1]), "+f"((c)[2]), "+f"((c)[3]) \
                 : "r"((a)[0]), "r"((a)[1]), "r"((a)[2]), "r"((a)[3]), \
                   "r"((b)[0]), "r"((b)[1]))

// ---------------- weight prep (fp16 weights; WBT gate-interleaved) ----------------
__global__ void prep_kernel(const float* __restrict__ w_ih, const float* __restrict__ w_hh,
                            const float* __restrict__ b_ih, const float* __restrict__ b_hh,
                            const float* __restrict__ W_ein, const float* __restrict__ b_ein,
                            const float* __restrict__ W_eout, const float* __restrict__ b_eout,
                            const float* __restrict__ b_iah, const float* __restrict__ b_oah) {
    int idx = blockIdx.x * blockDim.x + threadIdx.x;
    if (idx < 512 * 384) {  // g_WBTh [n'][k], n' = 4*j + g
        int np = idx / 384, k = idx - np * 384;
        int j = np >> 2, g = np & 3;
        int on = (g == 0) ? j : (g == 1) ? 128 + j : (g == 2) ? 256 + j : 384 + j;
        float v;
        if (on < 256)      v = (k < 256) ? w_ih[on * 256 + k] : w_hh[on * 128 + (k - 256)];
        else if (on < 384) v = (k < 256) ? w_ih[on * 256 + k] : 0.f;
        else               v = (k >= 256) ? w_hh[(on - 128) * 128 + (k - 256)] : 0.f;
        g_WBTh[idx] = __float2half_rn(v);
    }
    if (idx < 256 * 128) {  // [n][k]
        int n = idx >> 7, k = idx & 127;
        g_WETh[idx] = __float2half_rn((n < 128) ? W_ein[n * 128 + k] : W_eout[(n - 128) * 128 + k]);
    }
    if (idx < 512) {
        int j = idx >> 2, g = idx & 3;
        int on = (g == 0) ? j : (g == 1) ? 128 + j : (g == 2) ? 256 + j : 384 + j;
        g_biasBig[idx] = (on < 256) ? b_ih[on] + b_hh[on] : (on < 384) ? b_ih[on] : b_hh[on - 128];
    }
    if (idx < 256) {
        g_biasE[idx]  = (idx < 128) ? b_ein[idx] : b_eout[idx - 128];
        g_biasIO[idx] = (idx < 128) ? b_iah[idx] : b_oah[idx - 128];
    }
}

// ---------------- hidden -> fp16 ----------------
__global__ void cvt_hidden(const float* __restrict__ src) {
    int i = blockIdx.x * blockDim.x + threadIdx.x;
    float4 v = reinterpret_cast<const float4*>(src)[i];
    reinterpret_cast<uint2*>(g_Hh)[i] = cvt_pack_f16(v);
}

// ---------------- fp16 warp-MMA GEMM ----------------
// CTA tile 128x128, chunks of K=32.
// MODE 0: E   = hidden @ WET^T  -> g_ETh (transposed, fp16) [3-stage cp.async]
// MODE 1: MSG = A[b] @ ET[b]^T  -> g_MSGh (fp16) [X reg-prefetch, B cp.async]
// MODE 2: gates + fused GRU     -> g_H2h         [3-stage cp.async]
#define LDS_ 40        // row stride in halfs (80B): conflict-free for STS/cp.async + ldmatrix
#define PLANE_H 5120   // halfs per plane (128 x 40)
#define STAGE_B (2 * PLANE_H * 2)      // 20480 bytes per stage
#define SMEM3 (3 * STAGE_B)            // 61440 (modes 0/2)
#define SMEM2 (2 * STAGE_B)            // 40960 (mode 1)

template<int MODE>
__global__ void __launch_bounds__(256, 2) gemm_mma(const float* __restrict__ Xext) {
    extern __shared__ __align__(16) uint16_t smraw[];
    uint32_t smb = (uint32_t)__cvta_generic_to_shared(&smraw[0]);

    int tid = threadIdx.x;
    int wid = tid >> 5, lane = tid & 31;
    int n0 = blockIdx.x * 128;
    int m0 = blockIdx.y * 128;
    int bz = blockIdx.z;

    const int K1 = (MODE == 1) ? 256 : (MODE == 2) ? 384 : 128;
    const int nc = K1 >> 5;

    const int wm0 = (wid & 3) * 32;
    const int wn0 = (wid >> 2) * 64;

    float acc[2][8][4];
#pragma unroll
    for (int i = 0; i < 2; i++)
#pragma unroll
        for (int j = 0; j < 8; j++)
#pragma unroll
            for (int c = 0; c < 4; c++) acc[i][j][c] = 0.f;

    int am = lane & 15;
    int akh = (lane >> 4) << 3;
    int bnl = (lane & 7) + ((lane >> 4) << 3);
    int bkh = ((lane >> 3) & 1) << 3;

    auto compute = [&](uint32_t bufb) {
#pragma unroll
        for (int ks = 0; ks < 32; ks += 16) {
            uint32_t af[2][4];
#pragma unroll
            for (int i = 0; i < 2; i++) {
                uint32_t aoff = bufb + (uint32_t)((wm0 + i * 16 + am) * LDS_ + ks + akh) * 2;
                LDSM4(af[i], aoff);
            }
#pragma unroll
            for (int jp = 0; jp < 4; jp++) {
                uint32_t boff = bufb + (uint32_t)(PLANE_H + (wn0 + jp * 16 + bnl) * LDS_ + ks + bkh) * 2;
                uint32_t bf[4];
                LDSM4(bf, boff);
#pragma unroll
                for (int i = 0; i < 2; i++) {
#pragma unroll
                    for (int jj = 0; jj < 2; jj++) {
                        MMA_F16(acc[i][jp * 2 + jj], af[i], (bf + jj * 2));
                    }
                }
            }
        }
    };

    if constexpr (MODE == 1) {
        // ---- X = A (fp32, reg-prefetch + cvt + STS); B = ETh (fp16, cp.async) ----
        int r8 = tid >> 3, c4 = (tid & 7) * 4;
        uint2 xh[4];
        const float* Xs = Xext + (size_t)bz * 131072;
        const __half* Bh = g_ETh + (size_t)bz * 65536;
        const int xcol0 = (n0 >= 128) ? 256 : 0;
        auto ldgX = [&](int kt) {
#pragma unroll
            for (int p = 0; p < 4; p++)
                xh[p] = cvt_pack_f16(*reinterpret_cast<const float4*>(
                    Xs + (size_t)(m0 + p * 32 + r8) * 512 + kt + xcol0 + c4));
        };
        auto stsX = [&](int pb) {
#pragma unroll
            for (int p = 0; p < 4; p++)
                *reinterpret_cast<uint2*>(&smraw[(size_t)pb * (2 * PLANE_H) +
                                                 (p * 32 + r8) * LDS_ + c4]) = xh[p];
        };
        auto cpB = [&](int kt, int pb) {
            uint32_t sb = smb + (uint32_t)(pb * STAGE_B);
#pragma unroll
            for (int i = 0; i < 2; i++) {
                int t = tid + 256 * i, r = t >> 2, sg = t & 3;
                cp_async16(sb + (uint32_t)(PLANE_H + r * LDS_ + sg * 8) * 2,
                           Bh + (size_t)(n0 + r) * 256 + kt + sg * 8);
            }
            CP_COMMIT();
        };
        cpB(0, 0);
        ldgX(0);
        stsX(0);
        int pb = 0;
        for (int c = 0; c < nc; c++) {
            bool more = (c + 1 < nc);
            if (more) ldgX((c + 1) * 32);
            CP_WAIT0();
            __syncthreads();
            if (more) cpB((c + 1) * 32, pb ^ 1);
            compute(smb + (uint32_t)(pb * STAGE_B));
            if (more) stsX(pb ^ 1);
            pb ^= 1;
        }
    } else {
        // ---- 3-stage cp.async path: both operands fp16 in GMEM ----
        auto issue = [&](int c) {
            int kt = c * 32;
            uint32_t sb = smb + (uint32_t)((c % 3) * STAGE_B);
            const __half* xs; int ldx;
            const __half* bs; int ldbv;
            if (MODE == 2) {
                if (kt < 256) { xs = g_MSGh + (size_t)m0 * 256 + kt; ldx = 256; }
                else          { xs = g_Hh + (size_t)m0 * 128 + (kt - 256); ldx = 128; }
                bs = g_WBTh + (size_t)n0 * 384 + kt; ldbv = 384;
            } else {  // MODE 0
                xs = g_Hh + (size_t)m0 * 128 + kt; ldx = 128;
                bs = g_WETh + (size_t)n0 * 128 + kt; ldbv = 128;
            }
#pragma unroll
            for (int i = 0; i < 2; i++) {
                int t = tid + 256 * i, r = t >> 2, sg = t & 3;
                cp_async16(sb + (uint32_t)(r * LDS_ + sg * 8) * 2, xs + (size_t)r * ldx + sg * 8);
            }
#pragma unroll
            for (int i = 0; i < 2; i++) {
                int t = tid + 256 * i, r = t >> 2, sg = t & 3;
                cp_async16(sb + (uint32_t)(PLANE_H + r * LDS_ + sg * 8) * 2, bs + (size_t)r * ldbv + sg * 8);
            }
            CP_COMMIT();
        };
        issue(0);
        if (nc > 1) issue(1);
        for (int c = 0; c < nc; c++) {
            if (c + 1 < nc) CP_WAIT1(); else CP_WAIT0();
            __syncthreads();
            if (c + 2 < nc) issue(c + 2);
            compute(smb + (uint32_t)((c % 3) * STAGE_B));
        }
        __syncthreads();
    }

    // ---- epilogues ----
    int mrow = m0 + wm0 + (lane >> 2);
    int ncol = wn0 + (lane & 3) * 2;

    if (MODE == 2) {
        // Fused GRU on gate-interleaved preactivations -> g_H2h (fp16).
        float* sh = reinterpret_cast<float*>(&smraw[0]);   // hidden tile [128][32]
        float* shH2 = sh + 4096;                           // H2 tile [128][32]
        int jc0 = n0 >> 2;
#pragma unroll
        for (int p = 0; p < 4; p++) {
            int r = p * 32 + (tid >> 3), cg = (tid & 7) * 4;
            *reinterpret_cast<float4*>(&sh[r * 32 + cg]) =
                *reinterpret_cast<const float4*>(Xext + (size_t)(m0 + r) * 128 + jc0 + cg);
        }
        __syncthreads();
#pragma unroll
        for (int i = 0; i < 2; i++) {
#pragma unroll
            for (int j = 0; j < 8; j++) {
                int n = n0 + ncol + 8 * j;
                float* cc = acc[i][j];
                float g0 = cc[0] + g_biasBig[n];
                float g1 = cc[1] + g_biasBig[n + 1];
                float g2 = cc[2] + g_biasBig[n];
                float g3 = cc[3] + g_biasBig[n + 1];
                float s0 = (lane & 1) ? g0 : g2;
                float s1 = (lane & 1) ? g1 : g3;
                float r0 = __shfl_xor_sync(0xFFFFFFFFu, s0, 1);
                float r1 = __shfl_xor_sync(0xFFFFFFFFu, s1, 1);
                float a0, a1, a2, a3;
                if (lane & 1) { a0 = r0; a1 = r1; a2 = g2; a3 = g3; }
                else          { a0 = g0; a1 = g1; a2 = r0; a3 = r1; }
                int jl = (ncol + 8 * j) >> 2;
                int rl = wm0 + (lane >> 2) + 16 * i + ((lane & 1) ? 8 : 0);
                float hv = sh[rl * 32 + jl];
                float rg = 1.f / (1.f + expf(-a0));
                float zg = 1.f / (1.f + expf(-a1));
                float ng = tanhf(a2 + rg * a3);
                shH2[rl * 32 + jl] = hv - zg * (hv - ng);
            }
        }
        __syncthreads();
#pragma unroll
        for (int p = 0; p < 4; p++) {
            int r = p * 32 + (tid >> 3), cg = (tid & 7) * 4;
            float4 v = *reinterpret_cast<float4*>(&shH2[r * 32 + cg]);
            *reinterpret_cast<uint2*>(g_H2h + (size_t)(m0 + r) * 128 + jc0 + cg) = cvt_pack_f16(v);
        }
    } else if (MODE == 0) {
        int b = mrow >> 8, s = mrow & 255;
        __half* o = g_ETh + (size_t)b * 65536;
#pragma unroll
        for (int i = 0; i < 2; i++) {
            int s0 = s + i * 16;
#pragma unroll
            for (int j = 0; j < 8; j++) {
                int n = n0 + ncol + j * 8;
                float* cc = acc[i][j];
                o[(size_t)n * 256 + s0]           = __float2half_rn(cc[0] + g_biasE[n]);
                o[(size_t)(n + 1) * 256 + s0]     = __float2half_rn(cc[1] + g_biasE[n + 1]);
                o[(size_t)n * 256 + s0 + 8]       = __float2half_rn(cc[2] + g_biasE[n]);
                o[(size_t)(n + 1) * 256 + s0 + 8] = __float2half_rn(cc[3] + g_biasE[n + 1]);
            }
        }
    } else {  // MODE 1
        size_t rbase = (size_t)bz * 256 + mrow;
#pragma unroll
        for (int i = 0; i < 2; i++) {
            __half* o0 = g_MSGh + (rbase + i * 16) * 256;
            __half* o1 = o0 + 8 * 256;
#pragma unroll
            for (int j = 0; j < 8; j++) {
                int n = n0 + ncol + j * 8;
                float* cc = acc[i][j];
                *reinterpret_cast<__half2*>(o0 + n) =
                    __floats2half2_rn(cc[0] + g_biasIO[n], cc[1] + g_biasIO[n + 1]);
                *reinterpret_cast<__half2*>(o1 + n) =
                    __floats2half2_rn(cc[2] + g_biasIO[n], cc[3] + g_biasIO[n + 1]);
            }
        }
    }
}

// ---------------- nvalid + ht1 gather + q0 GEMV ----------------
__global__ void q0_kernel(const int* __restrict__ mask,
                          const float* __restrict__ W_q0, const float* __restrict__ b_q0) {
    __shared__ int ired[128];
    __shared__ float ht[128];
    int b = blockIdx.x, t = threadIdx.x;
    ired[t] = mask[b * 256 + t] + mask[b * 256 + 128 + t];
    __syncthreads();
    for (int off = 64; off; off >>= 1) {
        if (t < off) ired[t] += ired[t + off];
        __syncthreads();
    }
    int nv = ired[0];
    int li = nv - 1;
    ht[t] = __half2float(g_H2h[((size_t)b * 256 + li) * 128 + t]);
    __syncthreads();
    float acc = 0.f;
#pragma unroll 8
    for (int k = 0; k < 128; k++) acc += ht[k] * W_q0[t * 128 + k];
    g_q0v[b * 128 + t] = acc + b_q0[t];
    if (t == 0) g_nvalid[b] = nv;
}

// ---------------- fused attention (no Q12): scores & readout via v/z contraction ----------------
// score[h,j] = H2[j]·v[h] + c[h];  v[h,k] = sum_d W_q1[h*16+d,k]*q0[h,d];  c[h] = q0[h]·b_q1[h-blk]
// after softmaxes: y[h,d] = W_q2[h*16+d]·z[h] + G[h]*b_q2[h*16+d];  z[h,k] = sum_j g[h,j]*H2[j,k]
#define H2S_LD 132   // halfs per row (264B): uint2-aligned; worst LDS conflict 2-way
#define ATTN_SMEM (256 * H2S_LD * 2 + (128 + 1024 + 2048 + 1024 + 8 + 8) * 4)

__global__ void __launch_bounds__(512) attn2_kernel(
    const float* __restrict__ W_q1, const float* __restrict__ b_q1,
    const float* __restrict__ W_q2, const float* __restrict__ b_q2,
    float* __restrict__ out) {
    extern __shared__ __align__(16) char araw[];
    __half* H2s = reinterpret_cast<__half*>(araw);                 // [256][H2S_LD]
    float* q0s = reinterpret_cast<float*>(araw + 256 * H2S_LD * 2);  // 128
    float* v   = q0s + 128;    // [8][128]
    float* sc  = v + 1024;     // [8][256]
    float* zf  = sc + 2048;    // [8][128]
    float* ch  = zf + 1024;    // [8]
    float* Gh  = ch + 8;       // [8]

    int b = blockIdx.x, t = threadIdx.x;
    const __half* src = g_H2h + (size_t)b * 32768;

    // load H2 tile (fp16) + q0
    if (t < 128) q0s[t] = g_q0v[b * 128 + t];
#pragma unroll
    for (int i = 0; i < 16; i++) {
        int idx = t + 512 * i;            // uint2 (4 halfs) units; 32 per row
        int r = idx >> 5, c4 = (idx & 31) * 4;
        *reinterpret_cast<uint2*>(&H2s[r * H2S_LD + c4]) =
            *reinterpret_cast<const uint2*>(src + r * 128 + c4);
    }
    __syncthreads();

    // v[h][k] (2 per thread) + c[h]
#pragma unroll
    for (int e = t; e < 1024; e += 512) {
        int h = e >> 7, k = e & 127;
        const float* q0h = q0s + h * 16;
        float s = 0.f;
#pragma unroll
        for (int d = 0; d < 16; d++) s = fmaf(q0h[d], W_q1[(h * 16 + d) * 128 + k], s);
        v[h * 128 + k] = s;
    }
    if (t < 8) {
        float s = 0.f;
#pragma unroll
        for (int d = 0; d < 16; d++) s = fmaf(q0s[t * 16 + d], b_q1[t * 16 + d], s);
        ch[t] = s;
    }
    __syncthreads();

    // scores + sigmoid: sc[h][j]
#pragma unroll
    for (int e = t; e < 2048; e += 512) {
        int h = e >> 8, j = e & 255;
        const float* vh = v + h * 128;
        float s = ch[h];
#pragma unroll 8
        for (int k2 = 0; k2 < 64; k2++) {
            __half2 hv = *reinterpret_cast<__half2*>(&H2s[j * H2S_LD + 2 * k2]);
            float2 f = __half22float2(hv);
            s = fmaf(vh[2 * k2], f.x, s);
            s = fmaf(vh[2 * k2 + 1], f.y, s);
        }
        sc[h * 256 + j] = 1.f / (1.f + expf(-s));
    }
    __syncthreads();
    // per-head softmax over j (warps 0-7)
    {
        int w = t >> 5, lane = t & 31;
        if (w < 8) {
            float sum = 0.f;
            for (int j = lane; j < 256; j += 32) {
                float e = expf(sc[w * 256 + j]);
                sc[w * 256 + j] = e;
                sum += e;
            }
#pragma unroll
            for (int o = 16; o; o >>= 1) sum += __shfl_xor_sync(0xFFFFFFFFu, sum, o);
            float inv = 1.f / sum;
            for (int j = lane; j < 256; j += 32) sc[w * 256 + j] *= inv;
        }
    }
    __syncthreads();
    // per-j softmax over heads
    if (t < 256) {
        int j = t;
        float e[8], s = 0.f;
#pragma unroll
        for (int h = 0; h < 8; h++) { e[h] = expf(2.f * sc[h * 256 + j]); s += e[h]; }
        float inv = 1.f / s;
#pragma unroll
        for (int h = 0; h < 8; h++) sc[h * 256 + j] = e[h] * inv;
    }
    __syncthreads();

    // z[h][k] (one half2-column pair per thread) + G[h]
    {
        int h = t >> 6, k2 = t & 63;
        float zx = 0.f, zy = 0.f, gs = 0.f;
        const float* sch = sc + h * 256;
        for (int j = 0; j < 256; j++) {
            float g = sch[j];
            __half2 hv = *reinterpret_cast<__half2*>(&H2s[j * H2S_LD + 2 * k2]);
            float2 f = __half22float2(hv);
            zx = fmaf(g, f.x, zx);
            zy = fmaf(g, f.y, zy);
            gs += g;
        }
        zf[h * 128 + 2 * k2] = zx;
        zf[h * 128 + 2 * k2 + 1] = zy;
        if (k2 == 0) Gh[h] = gs;
    }
    __syncthreads();

    // y + write out
    if (t < 128) {
        int h = t >> 4;
        const float* zh = zf + h * 128;
        float s = Gh[h] * b_q2[t];
#pragma unroll 8
        for (int k = 0; k < 128; k++) s = fmaf(W_q2[t * 128 + k], zh[k], s);
        out[b * 128 + t] = (float)g_nvalid[b] * s;
    }
}

// ---------------- launch ----------------
extern "C" void kernel_launch(void* const* d_in, const int* in_sizes, int n_in,
                              void* d_out, int out_size) {
    const float* A      = (const float*)d_in[0];
    const float* hidden = (const float*)d_in[1];
    const int*   mask   = (const int*)d_in[2];
    const float* w_ih   = (const float*)d_in[3];
    const float* w_hh   = (const float*)d_in[4];
    const float* b_ih   = (const float*)d_in[5];
    const float* b_hh   = (const float*)d_in[6];
    const float* b_iah  = (const float*)d_in[7];
    const float* b_oah  = (const float*)d_in[8];
    const float* W_ein  = (const float*)d_in[9];
    const float* b_ein  = (const float*)d_in[10];
    const float* W_eout = (const float*)d_in[11];
    const float* b_eout = (const float*)d_in[12];
    const float* W_q0   = (const float*)d_in[13];
    const float* b_q0   = (const float*)d_in[14];
    const float* W_q1   = (const float*)d_in[15];
    const float* b_q1   = (const float*)d_in[16];
    const float* W_q2   = (const float*)d_in[17];
    const float* b_q2   = (const float*)d_in[18];
    float* out = (float*)d_out;

    static bool attr_done = false;
    if (!attr_done) {
        cudaFuncSetAttribute(gemm_mma<0>, cudaFuncAttributeMaxDynamicSharedMemorySize, SMEM3);
        cudaFuncSetAttribute(gemm_mma<1>, cudaFuncAttributeMaxDynamicSharedMemorySize, SMEM2);
        cudaFuncSetAttribute(gemm_mma<2>, cudaFuncAttributeMaxDynamicSharedMemorySize, SMEM3);
        cudaFuncSetAttribute(attn2_kernel, cudaFuncAttributeMaxDynamicSharedMemorySize, ATTN_SMEM);
        attr_done = true;
    }

    // 0) weight prep + hidden fp16
    prep_kernel<<<768, 256>>>(w_ih, w_hh, b_ih, b_hh, W_ein, b_ein, W_eout, b_eout,
                              b_iah, b_oah);
    cvt_hidden<<<4096, 256>>>(hidden);
    // 1) E^T -> g_ETh (fp16)
    gemm_mma<0><<<dim3(2, 256, 1), 256, SMEM3>>>(hidden);
    // 2) MSG = A @ E -> g_MSGh (fp16)
    gemm_mma<1><<<dim3(2, 2, 128), 256, SMEM2>>>(A);
    // 3) gates + fused GRU -> g_H2h
    gemm_mma<2><<<dim3(4, 256, 1), 256, SMEM3>>>(hidden);
    // 4) nvalid, ht1, q0
    q0_kernel<<<128, 128>>>(mask, W_q0, b_q0);
    // 5) fused attention readout (replaces Q12 GEMM + attn)
    attn2_kernel<<<128, 512, ATTN_SMEM>>>(W_q1, b_q1, W_q2, b_q2, out);
}